// round 1
// baseline (speedup 1.0000x reference)
#include <cuda_runtime.h>

// LGA: out[n,c,h,w] = sum_{i,j in 5x5} in1[n,c,h+i-2,w+j-2] * in2[n,i*5+j,h,w]
// Shapes fixed by the dataset: in1 [4,32,384,768] f32, in2 [4,25,384,768] f32.

#define NDIM 4
#define CDIM 32
#define HDIM 384
#define WDIM 768
#define KTAPS 25

#define TILE_W 64
#define TILE_H 8
#define SROWS (TILE_H + 4)   // 12
#define SCOLS (TILE_W + 4)   // 68
#define SPITCH 72            // padded pitch (even -> float2 aligned)
#define SELEMS (SROWS * SCOLS)  // 816

__global__ __launch_bounds__(256)
void lga_kernel(const float* __restrict__ in1,
                const float* __restrict__ in2,
                float* __restrict__ out) {
    __shared__ __align__(16) float tile[2][SROWS * SPITCH];

    const int tx = threadIdx.x;            // 0..31
    const int ty = threadIdx.y;            // 0..7
    const int tid = ty * 32 + tx;
    const int wbase = blockIdx.x * TILE_W;
    const int hbase = blockIdx.y * TILE_H;
    const int n = blockIdx.z;

    const int h = hbase + ty;              // this thread's output row
    const int w0 = wbase + 2 * tx;         // first of 2 output cols

    // ---- load 25 weight pairs (per-pixel taps) into registers, once ----
    float wa[KTAPS], wb[KTAPS];
    {
        const float* wp = in2 + ((size_t)n * KTAPS * HDIM + h) * WDIM + w0;
        const size_t tap_stride = (size_t)HDIM * WDIM;
#pragma unroll
        for (int t = 0; t < KTAPS; t++) {
            float2 v = *(const float2*)(wp + t * tap_stride);
            wa[t] = v.x;
            wb[t] = v.y;
        }
    }

    // ---- precompute cooperative-load offsets for the halo tile ----
    int  goff[4];
    bool gval[4];
    int  soff[4];
    bool sact[4];
#pragma unroll
    for (int k = 0; k < 4; k++) {
        int idx = tid + k * 256;
        int r  = idx / SCOLS;
        int cc = idx - r * SCOLS;
        int gy = hbase - 2 + r;
        int gx = wbase - 2 + cc;
        sact[k] = (idx < SELEMS);
        gval[k] = sact[k] && (gy >= 0) && (gy < HDIM) && (gx >= 0) && (gx < WDIM);
        goff[k] = gy * WDIM + gx;
        soff[k] = r * SPITCH + cc;
    }

    const size_t plane = (size_t)HDIM * WDIM;
    const float* in1n = in1 + (size_t)n * CDIM * plane;
    float* outn = out + (size_t)n * CDIM * plane;
    const size_t obase = (size_t)h * WDIM + w0;

    // ---- prefetch channel 0 and stage into buffer 0 ----
    float stage[4];
#pragma unroll
    for (int k = 0; k < 4; k++)
        stage[k] = gval[k] ? __ldg(in1n + goff[k]) : 0.0f;
#pragma unroll
    for (int k = 0; k < 4; k++)
        if (sact[k]) tile[0][soff[k]] = stage[k];
    __syncthreads();

    int p = 0;
#pragma unroll 1
    for (int c = 0; c < CDIM; c++) {
        // prefetch next channel while computing this one
        if (c + 1 < CDIM) {
            const float* in1c = in1n + (size_t)(c + 1) * plane;
#pragma unroll
            for (int k = 0; k < 4; k++)
                stage[k] = gval[k] ? __ldg(in1c + goff[k]) : 0.0f;
        }

        // compute 2 outputs from the smem window
        const float* basep = &tile[p][ty * SPITCH + 2 * tx];
        float acc0 = 0.0f, acc1 = 0.0f;
#pragma unroll
        for (int i = 0; i < 5; i++) {
            float2 d01 = *(const float2*)(basep + i * SPITCH + 0);
            float2 d23 = *(const float2*)(basep + i * SPITCH + 2);
            float2 d45 = *(const float2*)(basep + i * SPITCH + 4);
            const float d0 = d01.x, d1 = d01.y, d2 = d23.x,
                        d3 = d23.y, d4 = d45.x, d5 = d45.y;
            acc0 = fmaf(d0, wa[i * 5 + 0], acc0);
            acc1 = fmaf(d1, wb[i * 5 + 0], acc1);
            acc0 = fmaf(d1, wa[i * 5 + 1], acc0);
            acc1 = fmaf(d2, wb[i * 5 + 1], acc1);
            acc0 = fmaf(d2, wa[i * 5 + 2], acc0);
            acc1 = fmaf(d3, wb[i * 5 + 2], acc1);
            acc0 = fmaf(d3, wa[i * 5 + 3], acc0);
            acc1 = fmaf(d4, wb[i * 5 + 3], acc1);
            acc0 = fmaf(d4, wa[i * 5 + 4], acc0);
            acc1 = fmaf(d5, wb[i * 5 + 4], acc1);
        }

        *(float2*)(outn + (size_t)c * plane + obase) = make_float2(acc0, acc1);

        // stage next channel into the other buffer
        if (c + 1 < CDIM) {
#pragma unroll
            for (int k = 0; k < 4; k++)
                if (sact[k]) tile[p ^ 1][soff[k]] = stage[k];
        }
        __syncthreads();
        p ^= 1;
    }
}

extern "C" void kernel_launch(void* const* d_in, const int* in_sizes, int n_in,
                              void* d_out, int out_size) {
    const float* in1 = (const float*)d_in[0];
    const float* in2 = (const float*)d_in[1];
    float* out = (float*)d_out;

    dim3 block(32, 8);
    dim3 grid(WDIM / TILE_W, HDIM / TILE_H, NDIM);  // 12 x 48 x 4
    lga_kernel<<<grid, block>>>(in1, in2, out);
}